// round 17
// baseline (speedup 1.0000x reference)
#include <cuda_runtime.h>
#include <cuda_fp16.h>
#include <cstdint>

#define B_   16
#define L_   2048
#define H_   512
#define N_   64

// ---------------- fused-kernel dynamic smem layout (byte offsets) ------------
#define oWH  0          // W fp16 [128][72] = 18432 B
#define oA2  18432      // A2: 3 segs x [64][72] fp16 = 27648 B
#define oU   46080      // u tiles: 4 bufs x [32][72] fp16 = 18432 B
#define oD1  64512      // D1: 2 batches x [128][36] fp32 = 36864 B
#define oX   101376     // X tiles (k-major): 2 batches x [128][40] fp16 = 20480 B
#define oD2  121856     // D2 partials: 4 x [64][33] fp32 = 33792 B
#define SMEM_TOTAL 155648

// ---------------- scratch (__device__ globals) --------------------------------
__device__ __align__(16) __half gW  [H_ * 9216];    // per h: [128][72] fp16
__device__ __align__(16) __half gA2 [H_ * 13824];   // per h: 3 segs x [64][72]
__device__ __align__(16) float2 d_AbC[H_ * N_];     // Ab^C
__device__ __align__(16) float  d_ut [B_ * H_ * L_];
__device__ __align__(16) float  d_yt [B_ * H_ * L_];

__device__ __forceinline__ float2 cmul(float2 a, float2 b) {
    return make_float2(a.x * b.x - a.y * b.y, a.x * b.y + a.y * b.x);
}

// ---------------- PTX helpers -------------------------------------------------
__device__ __forceinline__ uint32_t smem_to_u32(const void* p) {
    uint32_t a;
    asm("{ .reg .u64 t; cvta.to.shared.u64 t, %1; cvt.u32.u64 %0, t; }" : "=r"(a) : "l"(p));
    return a;
}
__device__ __forceinline__ void ldm_x4(uint32_t* r, uint32_t addr) {
    asm volatile("ldmatrix.sync.aligned.m8n8.x4.shared.b16 {%0,%1,%2,%3}, [%4];"
                 : "=r"(r[0]), "=r"(r[1]), "=r"(r[2]), "=r"(r[3]) : "r"(addr));
}
__device__ __forceinline__ void ldm_x4t(uint32_t* r, uint32_t addr) {
    asm volatile("ldmatrix.sync.aligned.m8n8.x4.trans.shared.b16 {%0,%1,%2,%3}, [%4];"
                 : "=r"(r[0]), "=r"(r[1]), "=r"(r[2]), "=r"(r[3]) : "r"(addr));
}
__device__ __forceinline__ void mma16816h(float* d, const uint32_t* a, const uint32_t* b) {
    asm volatile("mma.sync.aligned.m16n8k16.row.col.f32.f16.f16.f32 "
                 "{%0,%1,%2,%3}, {%4,%5,%6,%7}, {%8,%9}, {%0,%1,%2,%3};"
                 : "+f"(d[0]), "+f"(d[1]), "+f"(d[2]), "+f"(d[3])
                 : "r"(a[0]), "r"(a[1]), "r"(a[2]), "r"(a[3]), "r"(b[0]), "r"(b[1]));
}

__device__ __forceinline__ void put1h(__half* t, int idx, float v) {
    t[idx] = __float2half_rn(v);
}

// ---------------- precompute (split across 2 launches) ------------------------
__global__ void precompute_kernel(const float* __restrict__ Lr,
                                  const float* __restrict__ Li,
                                  const float* __restrict__ Br,
                                  const float* __restrict__ Bi,
                                  const float* __restrict__ Cr,
                                  const float* __restrict__ Ci,
                                  const float* __restrict__ logdt,
                                  const float* __restrict__ Din,
                                  int hofs) {
    int h = blockIdx.x + hofs;
    int n = threadIdx.x;             // 64 threads
    int lane = n & 31, wid = n >> 5;

    float dt  = expf(logdt[h]);
    float lr  = Lr[n], li = Li[n];
    float er = expf(dt * lr);
    float s, c;
    sincosf(dt * li, &s, &c);
    float2 Ab = make_float2(er * c, er * s);

    float dr = lr + 1e-8f, di = li;
    float inv = 1.0f / (dr * dr + di * di);
    float2 Am1 = make_float2(Ab.x - 1.0f, Ab.y);
    float2 Bc  = make_float2(Br[h * N_ + n], Bi[h * N_ + n]);
    float2 num = cmul(Bc, Am1);
    float2 Bb  = make_float2((num.x * dr + num.y * di) * inv,
                             (num.y * dr - num.x * di) * inv);
    float2 Cc  = make_float2(Cr[h * N_ + n], Ci[h * N_ + n]);
    float2 CB  = cmul(Cc, Bb);

    __shared__ float sKpart[64][2];
    __shared__ float sKd[64];

    __half* WH  = gW + (size_t)h * 9216;             // [128][72]
    __half* s0  = gA2 + (size_t)h * 13824;           // Mr
    __half* s1  = s0 + 4608;                         // -Mi
    __half* s2  = s0 + 9216;                         // Toeplitz+D

    float2 p = make_float2(1.0f, 0.0f);              // Ab^e
    for (int e = 0; e < 64; e++) {
        float2 w = cmul(p, Bb);                      // = Ab^{63-j} Bb at j = 63-e
        int j = 63 - e;
        put1h(WH, n * 72 + j, w.x);                  // rows 0..63 : real
        put1h(WH, (64 + n) * 72 + j, w.y);           // rows 64..127 : imag
        float kv = CB.x * p.x - CB.y * p.y;          // K[e] partial (this n)
        #pragma unroll
        for (int off = 16; off; off >>= 1) kv += __shfl_xor_sync(0xffffffffu, kv, off);
        if (lane == 0) sKpart[e][wid] = kv;
        p = cmul(p, Ab);                             // Ab^{e+1}
        float2 m = cmul(Cc, p);                      // M[i=e][n]
        put1h(s0, e * 72 + n, m.x);
        put1h(s1, e * 72 + n, -m.y);
    }
    d_AbC[h * N_ + n] = p;                           // Ab^C
    __syncthreads();
    sKd[n] = sKpart[n][0] + sKpart[n][1];            // K[d = n]
    __syncthreads();

    float Dh = Din[h];
    for (int i = 0; i < 64; i++) {                   // Toeplitz + D on diagonal
        float v = (i > n) ? sKd[i - n] : (i == n ? sKd[0] + Dh : 0.0f);
        put1h(s2, i * 72 + n, v);
    }
}

// ---------------- transposes (float4 both gmem sides) --------------------------
__global__ void transpose_BLH_to_BHL(const float* __restrict__ in, float* __restrict__ out) {
    __shared__ float tile[32][36];
    int b = blockIdx.z;
    int h0 = blockIdx.x * 32, l0 = blockIdx.y * 32;
    int t = threadIdx.x;                 // 256
    {
        int l = t >> 3, hq = t & 7;
        float4 v = *(const float4*)(in + ((size_t)b * L_ + l0 + l) * H_ + h0 + hq * 4);
        tile[hq * 4 + 0][l] = v.x;
        tile[hq * 4 + 1][l] = v.y;
        tile[hq * 4 + 2][l] = v.z;
        tile[hq * 4 + 3][l] = v.w;
    }
    __syncthreads();
    {
        int hh = t >> 3, lq = t & 7;
        float4 w = *(const float4*)&tile[hh][lq * 4];
        *(float4*)(out + ((size_t)b * H_ + h0 + hh) * L_ + l0 + lq * 4) = w;
    }
}

__global__ void transpose_BHL_to_BLH(const float* __restrict__ in, float* __restrict__ out) {
    __shared__ float tile[32][36];
    int b = blockIdx.z;
    int l0 = blockIdx.x * 32, h0 = blockIdx.y * 32;
    int t = threadIdx.x;                 // 256
    {
        int hh = t >> 3, lq = t & 7;
        float4 v = *(const float4*)(in + ((size_t)b * H_ + h0 + hh) * L_ + l0 + lq * 4);
        tile[lq * 4 + 0][hh] = v.x;
        tile[lq * 4 + 1][hh] = v.y;
        tile[lq * 4 + 2][hh] = v.z;
        tile[lq * 4 + 3][hh] = v.w;
    }
    __syncthreads();
    {
        int l = t >> 3, hq = t & 7;
        float4 w = *(const float4*)&tile[l][hq * 4];
        *(float4*)(out + ((size_t)b * L_ + l0 + l) * H_ + h0 + hq * 4) = w;
    }
}

// ---------------- u staging: fp32 -> fp16 padded tile -------------------------
__device__ __forceinline__ void stage_u1(char* smc, const float* __restrict__ up,
                                         int buf, int tid) {
    float4 v = ((const float4*)up)[tid];
    __half* uh = (__half*)(smc + oU + buf * 4608);
    int idx = (tid >> 4) * 72 + (tid & 15) * 4;
    __half2 p0; p0.x = __float2half_rn(v.x); p0.y = __float2half_rn(v.y);
    __half2 p1; p1.x = __float2half_rn(v.z); p1.y = __float2half_rn(v.w);
    *(__half2*)(uh + idx)     = p0;
    *(__half2*)(uh + idx + 2) = p1;
}

// ---------------- fused HMMA kernel: x4 B-loads, 3 syncs/iter -----------------
extern __shared__ char smc[];
__global__ __launch_bounds__(512, 1) void fused_kernel() {
    int h   = blockIdx.y;
    int b0  = blockIdx.x * 8;
    int tid = threadIdx.x;
    int w   = tid >> 5, lane = tid & 31;

    uint32_t sb = smem_to_u32(smc);

    // ---- stage operators: W 18432 B + A2 27648 B
    {
        const float4* s = (const float4*)(gW + (size_t)h * 9216);
        float4* d = (float4*)(smc + oWH);
        for (int i = tid; i < 1152; i += 512) d[i] = s[i];
        s = (const float4*)(gA2 + (size_t)h * 13824);
        d = (float4*)(smc + oA2);
        for (int i = tid; i < 1728; i += 512) d[i] = s[i];
    }
    stage_u1(smc, d_ut + ((size_t)b0 * H_ + h) * L_, 0, tid);
    stage_u1(smc, d_ut + ((size_t)(b0 + 1) * H_ + h) * L_, 1, tid);

    // scan constants: n = tid>>3, q = tid&7
    int sn = tid >> 3, sq = tid & 7;
    float2 a1  = d_AbC[h * 64 + sn];
    float2 a2c = cmul(a1, a1);
    float2 a3c = cmul(a2c, a1);
    float2 a4c = cmul(a2c, a2c);
    float2 a8c = cmul(a4c, a4c);
    float2 a16c = cmul(a8c, a8c);
    __syncthreads();

    uint32_t laneA  = (uint32_t)(((lane & 15) * 72 + (lane >> 4) * 8) * 2);
    // x4 B-load lane map: lanes 0-15 -> nt0 frag, lanes 16-31 -> nt1 frag
    uint32_t laneB4 = (uint32_t)(((lane & 7) * 72 + ((lane >> 3) & 1) * 8) * 2
                                 + (lane >> 4) * 1152);
    // x4 trans lane map for k-major X tiles (80B rows): lanes 16-31 -> +16B col
    uint32_t laneXT = (uint32_t)((lane & 15) * 80 + (lane >> 4) * 16);

    // MMA1 tiling: mq1 = 16-row m-tile, nh1 = 16-col n-half; W frags cached
    int mq1 = w & 7, nh1 = w >> 3;
    uint32_t w1A[4][4];
    {
        uint32_t w1Hb = sb + oWH + (uint32_t)(mq1 * 16 * 144) + laneA;
        #pragma unroll
        for (int kt = 0; kt < 4; kt++) ldm_x4(w1A[kt], w1Hb + (uint32_t)(kt * 32));
    }

    // MMA2 tiling: mq2 m-tile, nh2 n-half, ng k-half (6 k-chunks each); cached
    int mq2 = w & 3, nh2 = (w >> 2) & 1, ng = w >> 3;
    uint32_t a2A[6][4];
    #pragma unroll
    for (int kcl = 0; kcl < 6; kcl++) {
        int kc = ng * 6 + kcl, sg = kc >> 2, kt = kc & 3;
        uint32_t base = sb + oA2 + (uint32_t)(sg * 9216 + mq2 * 16 * 144 + kt * 32) + laneA;
        ldm_x4(a2A[kcl], base);
    }

    float* sD1f = (float*)(smc + oD1);
    float* sD2f = (float*)(smc + oD2);
    int gid = lane >> 2, tq = lane & 3;

    for (int it = 0; it < 4; it++) {
        int bb0 = (2 * it) & 3, bb1 = (2 * it + 1) & 3;

        // ======== Phase A: store y(it-1) + MMA1(it) both batches ========
        if (it > 0) {
            int bt = tid >> 8, t = tid & 255;
            float* sD2a = sD2f + bt * 2 * 2112;
            float* yp = d_yt + ((size_t)(b0 + 2 * it - 2 + bt) * H_ + h) * L_;
            #pragma unroll
            for (int rep = 0; rep < 2; rep++) {
                int idx = rep * 256 + t;
                int c = idx >> 4, i0 = (idx & 15) * 4;
                float4 y4;
                y4.x = sD2a[(i0 + 0) * 33 + c] + sD2a[2112 + (i0 + 0) * 33 + c];
                y4.y = sD2a[(i0 + 1) * 33 + c] + sD2a[2112 + (i0 + 1) * 33 + c];
                y4.z = sD2a[(i0 + 2) * 33 + c] + sD2a[2112 + (i0 + 2) * 33 + c];
                y4.w = sD2a[(i0 + 3) * 33 + c] + sD2a[2112 + (i0 + 3) * 33 + c];
                *(float4*)(yp + c * 64 + i0) = y4;
            }
        }
        {
            uint32_t uh0 = sb + oU + (uint32_t)(bb0 * 4608 + nh1 * 2304) + laneB4;
            uint32_t uh1 = sb + oU + (uint32_t)(bb1 * 4608 + nh1 * 2304) + laneB4;
            float acc[2][2][4];
            #pragma unroll
            for (int bt = 0; bt < 2; bt++)
                #pragma unroll
                for (int nt = 0; nt < 2; nt++)
                    #pragma unroll
                    for (int i = 0; i < 4; i++) acc[bt][nt][i] = 0.f;
            #pragma unroll
            for (int kt = 0; kt < 4; kt++) {
                uint32_t ko = kt * 32;
                uint32_t bq[4];
                ldm_x4(bq, uh0 + ko);
                mma16816h(acc[0][0], w1A[kt], bq);
                mma16816h(acc[0][1], w1A[kt], bq + 2);
                ldm_x4(bq, uh1 + ko);
                mma16816h(acc[1][0], w1A[kt], bq);
                mma16816h(acc[1][1], w1A[kt], bq + 2);
            }
            #pragma unroll
            for (int bt = 0; bt < 2; bt++)
                #pragma unroll
                for (int nt = 0; nt < 2; nt++) {
                    int c0 = nh1 * 16 + nt * 8 + tq * 2;
                    int r0 = mq1 * 16 + gid;
                    float* D1b = sD1f + bt * 4608;
                    D1b[r0 * 36 + c0]           = acc[bt][nt][0];
                    D1b[r0 * 36 + c0 + 1]       = acc[bt][nt][1];
                    D1b[(r0 + 8) * 36 + c0]     = acc[bt][nt][2];
                    D1b[(r0 + 8) * 36 + c0 + 1] = acc[bt][nt][3];
                }
        }
        __syncthreads();

        // ======== Phase B: scan both batches + emit k-major X; stage u ========
        #pragma unroll
        for (int bt = 0; bt < 2; bt++) {
            float* D1b = sD1f + bt * 4608;
            __half* Xt = (__half*)(smc + oX + bt * 10240);   // [128 k][40 c]

            float4 gr4 = *(const float4*)(D1b + sn * 36 + sq * 4);
            float4 gi4 = *(const float4*)(D1b + (64 + sn) * 36 + sq * 4);
            float h0r = gr4.x, h0i = gi4.x;
            float h1r = a1.x * h0r - a1.y * h0i + gr4.y;
            float h1i = a1.x * h0i + a1.y * h0r + gi4.y;
            float h2r = a1.x * h1r - a1.y * h1i + gr4.z;
            float h2i = a1.x * h1i + a1.y * h1r + gi4.z;
            float Sr  = a1.x * h2r - a1.y * h2i + gr4.w;
            float Si  = a1.x * h2i + a1.y * h2r + gi4.w;
            float tr, ti;
            tr = __shfl_up_sync(0xffffffffu, Sr, 1, 8);
            ti = __shfl_up_sync(0xffffffffu, Si, 1, 8);
            if (sq >= 1) { Sr += a4c.x * tr - a4c.y * ti;  Si += a4c.x * ti + a4c.y * tr; }
            tr = __shfl_up_sync(0xffffffffu, Sr, 2, 8);
            ti = __shfl_up_sync(0xffffffffu, Si, 2, 8);
            if (sq >= 2) { Sr += a8c.x * tr - a8c.y * ti;  Si += a8c.x * ti + a8c.y * tr; }
            tr = __shfl_up_sync(0xffffffffu, Sr, 4, 8);
            ti = __shfl_up_sync(0xffffffffu, Si, 4, 8);
            if (sq >= 4) { Sr += a16c.x * tr - a16c.y * ti; Si += a16c.x * ti + a16c.y * tr; }
            float X0r = __shfl_up_sync(0xffffffffu, Sr, 1, 8);
            float X0i = __shfl_up_sync(0xffffffffu, Si, 1, 8);
            if (sq == 0) { X0r = 0.f; X0i = 0.f; }

            float v1r = a1.x * X0r - a1.y * X0i + h0r;
            float v1i = a1.x * X0i + a1.y * X0r + h0i;
            float v2r = a2c.x * X0r - a2c.y * X0i + h1r;
            float v2i = a2c.x * X0i + a2c.y * X0r + h1i;
            float v3r = a3c.x * X0r - a3c.y * X0i + h2r;
            float v3i = a3c.x * X0i + a3c.y * X0r + h2i;

            __half2 r01, r23, i01, i23;
            r01.x = __float2half_rn(X0r);  r01.y = __float2half_rn(v1r);
            r23.x = __float2half_rn(v2r);  r23.y = __float2half_rn(v3r);
            i01.x = __float2half_rn(X0i);  i01.y = __float2half_rn(v1i);
            i23.x = __float2half_rn(v2i);  i23.y = __float2half_rn(v3i);
            uint2 pk;
            pk.x = *(uint32_t*)&r01;  pk.y = *(uint32_t*)&r23;
            *(uint2*)(Xt + sn * 40 + sq * 4) = pk;          // xr row sn
            pk.x = *(uint32_t*)&i01;  pk.y = *(uint32_t*)&i23;
            *(uint2*)(Xt + (64 + sn) * 40 + sq * 4) = pk;   // xi row 64+sn
        }
        if (it < 3) {
            stage_u1(smc, d_ut + ((size_t)(b0 + 2 * it + 2) * H_ + h) * L_, (2 * it + 2) & 3, tid);
            stage_u1(smc, d_ut + ((size_t)(b0 + 2 * it + 3) * H_ + h) * L_, (2 * it + 3) & 3, tid);
        }
        __syncthreads();

        // ======== Phase C: MMA2 both batches (x4 trans B; D2 separate) ========
        #pragma unroll
        for (int bt = 0; bt < 2; bt++) {
            uint32_t uhBp = sb + oU + (uint32_t)(((2 * it + bt) & 3) * 4608 + nh2 * 2304) + laneB4;
            uint32_t xb   = sb + oX + (uint32_t)(bt * 10240 + nh2 * 32) + laneXT;
            float acc[2][4];
            #pragma unroll
            for (int nt = 0; nt < 2; nt++)
                #pragma unroll
                for (int i = 0; i < 4; i++) acc[nt][i] = 0.f;
            #pragma unroll
            for (int kcl = 0; kcl < 6; kcl++) {
                int kc = ng * 6 + kcl, sg = kc >> 2, kt = kc & 3;
                uint32_t bq[4];
                if (sg == 2) {
                    ldm_x4(bq, uhBp + (uint32_t)(kt * 32));
                } else {
                    ldm_x4t(bq, xb + (uint32_t)((sg * 64 + kt * 16) * 80));
                }
                mma16816h(acc[0], a2A[kcl], bq);
                mma16816h(acc[1], a2A[kcl], bq + 2);
            }
            float* sD2 = sD2f + (bt * 2 + ng) * 2112;
            #pragma unroll
            for (int nt = 0; nt < 2; nt++) {
                int c0 = nh2 * 16 + nt * 8 + tq * 2;
                int i0 = mq2 * 16 + gid;
                sD2[i0 * 33 + c0]           = acc[nt][0];
                sD2[i0 * 33 + c0 + 1]       = acc[nt][1];
                sD2[(i0 + 8) * 33 + c0]     = acc[nt][2];
                sD2[(i0 + 8) * 33 + c0 + 1] = acc[nt][3];
            }
        }
        __syncthreads();
    }

    // ---- final y store (batches 6,7)
    {
        int bt = tid >> 8, t = tid & 255;
        float* sD2a = sD2f + bt * 2 * 2112;
        float* yp = d_yt + ((size_t)(b0 + 6 + bt) * H_ + h) * L_;
        #pragma unroll
        for (int rep = 0; rep < 2; rep++) {
            int idx = rep * 256 + t;
            int c = idx >> 4, i0 = (idx & 15) * 4;
            float4 y4;
            y4.x = sD2a[(i0 + 0) * 33 + c] + sD2a[2112 + (i0 + 0) * 33 + c];
            y4.y = sD2a[(i0 + 1) * 33 + c] + sD2a[2112 + (i0 + 1) * 33 + c];
            y4.z = sD2a[(i0 + 2) * 33 + c] + sD2a[2112 + (i0 + 2) * 33 + c];
            y4.w = sD2a[(i0 + 3) * 33 + c] + sD2a[2112 + (i0 + 3) * 33 + c];
            *(float4*)(yp + c * 64 + i0) = y4;
        }
    }
}

// ---------------- launch --------------------------------------------------------
extern "C" void kernel_launch(void* const* d_in, const int* in_sizes, int n_in,
                              void* d_out, int out_size) {
    const float* u     = (const float*)d_in[0];
    const float* Lr    = (const float*)d_in[1];
    const float* Li    = (const float*)d_in[2];
    const float* Br    = (const float*)d_in[3];
    const float* Bi    = (const float*)d_in[4];
    const float* Cr    = (const float*)d_in[5];
    const float* Ci    = (const float*)d_in[6];
    const float* logdt = (const float*)d_in[7];
    const float* D     = (const float*)d_in[8];
    float* out = (float*)d_out;

    float* ut_ptr; cudaGetSymbolAddress((void**)&ut_ptr, d_ut);
    float* yt_ptr; cudaGetSymbolAddress((void**)&yt_ptr, d_yt);

    cudaFuncSetAttribute(fused_kernel, cudaFuncAttributeMaxDynamicSharedMemorySize, SMEM_TOTAL);

    precompute_kernel<<<H_ / 2, N_>>>(Lr, Li, Br, Bi, Cr, Ci, logdt, D, 0);
    precompute_kernel<<<H_ / 2, N_>>>(Lr, Li, Br, Bi, Cr, Ci, logdt, D, H_ / 2);
    transpose_BLH_to_BHL<<<dim3(H_ / 32, L_ / 32, B_), 256>>>(u, ut_ptr);
    fused_kernel<<<dim3(2, H_), 512, SMEM_TOTAL>>>();
    transpose_BHL_to_BLH<<<dim3(L_ / 32, H_ / 32, B_), 256>>>(yt_ptr, out);
}